// round 2
// baseline (speedup 1.0000x reference)
#include <cuda_runtime.h>
#include <cuda_bf16.h>

// EmbeddingSumConcat: out[b, f*E+e] = sum_{l < lengths[b,f]} tables[f, ids[b,f,l], e]
// B=4096, F=32, V=100000, L=20, E=64.
// NOTE: JAX runs x64-disabled by default, so ids/lengths are int32 despite the
// reference saying jnp.int64. tables/out are fp32.

#define EB_B 4096
#define EB_F 32
#define EB_V 100000
#define EB_L 20
#define EB_E 64
#define EB_V4 (EB_E / 4)   // 16 float4 per row

__global__ __launch_bounds__(256, 8) void embbag_kernel(
    const int*    __restrict__ ids,      // int32 [B, F, L]
    const int*    __restrict__ lengths,  // int32 [B, F]
    const float4* __restrict__ tables,   // fp32  [F, V, E/4]
    float4*       __restrict__ out)      // fp32  [B, F, E/4]
{
    int tid = blockIdx.x * 256 + threadIdx.x;       // 0 .. B*F*V4-1
    int v    = tid & (EB_V4 - 1);                   // float4 lane within row (0..15)
    int cell = tid >> 4;                            // f-major: cell = f*B + b
    int b    = cell & (EB_B - 1);                   // B = 4096 = 2^12
    int f    = cell >> 12;

    size_t bf = (size_t)b * EB_F + f;
    int n = lengths[bf];                            // 0..20
    const int*    idp  = ids + bf * EB_L;
    const float4* base = tables + (size_t)f * EB_V * EB_V4;

    // Prefetch all L ids (always in-bounds; dense [B,F,L] buffer).
    // Breaks id-load -> gather dependency; gives MLP across the 20 gathers.
    int idbuf[EB_L];
#pragma unroll
    for (int l = 0; l < EB_L; l++) {
        int id = idp[l];
        // Free safety clamp (no-op for valid ids): wrong dtype/model shows up
        // as rel_err, not an illegal access.
        idbuf[l] = min(max(id, 0), EB_V - 1);
    }

    float4 acc = make_float4(0.f, 0.f, 0.f, 0.f);
#pragma unroll
    for (int l = 0; l < EB_L; l++) {
        if (l < n) {
            float4 r = __ldg(&base[(size_t)idbuf[l] * EB_V4 + v]);
            acc.x += r.x; acc.y += r.y; acc.z += r.z; acc.w += r.w;
        }
    }

    out[bf * EB_V4 + v] = acc;
}

extern "C" void kernel_launch(void* const* d_in, const int* in_sizes, int n_in,
                              void* d_out, int out_size) {
    const int*    ids     = (const int*)d_in[0];    // int32 [B,F,L]
    const int*    lengths = (const int*)d_in[1];    // int32 [B,F]
    const float4* tables  = (const float4*)d_in[2]; // fp32  [F,V,E]
    float4*       out     = (float4*)d_out;         // fp32  [B,F*E]

    int total = EB_B * EB_F * EB_V4;                // 2,097,152 threads
    embbag_kernel<<<total / 256, 256>>>(ids, lengths, tables, out);
}

// round 3
// speedup vs baseline: 1.0793x; 1.0793x over previous
#include <cuda_runtime.h>
#include <cuda_bf16.h>

// EmbeddingSumConcat: out[b, f*E+e] = sum_{l < lengths[b,f]} tables[f, ids[b,f,l], e]
// B=4096, F=32, V=100000, L=20, E=64. ids/lengths int32 (JAX x64 disabled),
// tables/out fp32.

#define EB_B 4096
#define EB_F 32
#define EB_V 100000
#define EB_L 20
#define EB_E 64
#define EB_V4 (EB_E / 4)   // 16 float4 per row

__global__ __launch_bounds__(256, 8) void embbag_kernel(
    const int*    __restrict__ ids,      // int32 [B, F, L]
    const int*    __restrict__ lengths,  // int32 [B, F]
    const float4* __restrict__ tables,   // fp32  [F, V, E/4]
    float4*       __restrict__ out)      // fp32  [B, F, E/4]
{
    int tid = blockIdx.x * 256 + threadIdx.x;       // 0 .. B*F*V4-1
    int v    = tid & (EB_V4 - 1);                   // float4 lane within row (0..15)
    int cell = tid >> 4;                            // f-major: cell = f*B + b
    int b    = cell & (EB_B - 1);                   // B = 4096 = 2^12
    int f    = cell >> 12;

    size_t bf = (size_t)b * EB_F + f;
    int n = lengths[bf];                            // 0..20
    const float4* base = tables + (size_t)f * EB_V * EB_V4;

    // Ids for this cell: 80 bytes at a 16B-aligned offset (bf*80).
    // Load as 5x int4 instead of 20x scalar LDG: 4x fewer LSU slots, and all
    // 16 lanes of the cell-group hit the same sectors (hardware broadcast).
    const int4* idp4 = (const int4*)(ids + bf * EB_L);
    int idbuf[EB_L];
#pragma unroll
    for (int q = 0; q < EB_L / 4; q++) {
        int4 w = __ldg(&idp4[q]);
        idbuf[q * 4 + 0] = min(max(w.x, 0), EB_V - 1);
        idbuf[q * 4 + 1] = min(max(w.y, 0), EB_V - 1);
        idbuf[q * 4 + 2] = min(max(w.z, 0), EB_V - 1);
        idbuf[q * 4 + 3] = min(max(w.w, 0), EB_V - 1);
    }

    float4 acc = make_float4(0.f, 0.f, 0.f, 0.f);
#pragma unroll
    for (int l = 0; l < EB_L; l++) {
        if (l < n) {
            float4 r = __ldg(&base[(size_t)idbuf[l] * EB_V4 + v]);
            acc.x += r.x; acc.y += r.y; acc.z += r.z; acc.w += r.w;
        }
    }

    // Streaming store: output is written once and never re-read; keep it out
    // of L2 so the table's active column working set stays resident.
    __stcs(&out[bf * EB_V4 + v], acc);
}

extern "C" void kernel_launch(void* const* d_in, const int* in_sizes, int n_in,
                              void* d_out, int out_size) {
    const int*    ids     = (const int*)d_in[0];    // int32 [B,F,L]
    const int*    lengths = (const int*)d_in[1];    // int32 [B,F]
    const float4* tables  = (const float4*)d_in[2]; // fp32  [F,V,E]
    float4*       out     = (float4*)d_out;         // fp32  [B,F*E]

    int total = EB_B * EB_F * EB_V4;                // 2,097,152 threads
    embbag_kernel<<<total / 256, 256>>>(ids, lengths, tables, out);
}